// round 15
// baseline (speedup 1.0000x reference)
#include <cuda_runtime.h>
#include <cuda_bf16.h>
#include <cuda_fp8.h>
#include <cstdint>

#define NT 256

// Fragment-major fp8(e4m3) weights: each uint4 = one lane's m16n8k32 A-fragment (a0..a3)
// conv2: [9 tap][8 mblk][4 kblk][32 lane] = 9216 uint4
// conv3: [9 tap][4 mblk][4 kblk][32 lane] = 4608 uint4
// conv4: [9 tap][4 mblk][2 kblk][32 lane] = 2304 uint4
__device__ uint4 g_w2f8[9216];
__device__ uint4 g_w3f8[4608];
__device__ uint4 g_w4f8[2304];

__device__ __forceinline__ uint32_t pack4f8(float a, float b, float c, float d) {
    uint32_t r = (uint32_t)__nv_cvt_float_to_fp8(a, __NV_SATFINITE, __NV_E4M3);
    r |= (uint32_t)__nv_cvt_float_to_fp8(b, __NV_SATFINITE, __NV_E4M3) << 8;
    r |= (uint32_t)__nv_cvt_float_to_fp8(c, __NV_SATFINITE, __NV_E4M3) << 16;
    r |= (uint32_t)__nv_cvt_float_to_fp8(d, __NV_SATFINITE, __NV_E4M3) << 24;
    return r;
}
__device__ __forceinline__ float f8tof(unsigned char b) {
    return __half2float(__nv_cvt_fp8_to_halfraw(b, __NV_E4M3));
}
__device__ __forceinline__ unsigned char f2f8(float x) {
    return (unsigned char)__nv_cvt_float_to_fp8(x, __NV_SATFINITE, __NV_E4M3);
}

__global__ void convert_weights(const float* __restrict__ w2,
                                const float* __restrict__ w3,
                                const float* __restrict__ w4) {
    int gid = blockIdx.x * blockDim.x + threadIdx.x;
    int stride = gridDim.x * blockDim.x;
    for (int u = gid; u < 9216; u += stride) {
        int lane = u & 31, kb = (u >> 5) & 3, mb = (u >> 7) & 7, tap = u >> 10;
        int r = lane >> 2, c0 = (lane & 3) * 4;
        int co = mb * 16 + r, ci = kb * 32 + c0;
        const float* Wt = w2 + tap * 16384;  // [ci][co], 128-co stride
        uint4 v;
        v.x = pack4f8(Wt[ci * 128 + co], Wt[(ci + 1) * 128 + co],
                      Wt[(ci + 2) * 128 + co], Wt[(ci + 3) * 128 + co]);
        v.y = pack4f8(Wt[ci * 128 + co + 8], Wt[(ci + 1) * 128 + co + 8],
                      Wt[(ci + 2) * 128 + co + 8], Wt[(ci + 3) * 128 + co + 8]);
        v.z = pack4f8(Wt[(ci + 16) * 128 + co], Wt[(ci + 17) * 128 + co],
                      Wt[(ci + 18) * 128 + co], Wt[(ci + 19) * 128 + co]);
        v.w = pack4f8(Wt[(ci + 16) * 128 + co + 8], Wt[(ci + 17) * 128 + co + 8],
                      Wt[(ci + 18) * 128 + co + 8], Wt[(ci + 19) * 128 + co + 8]);
        g_w2f8[u] = v;
    }
    for (int u = gid; u < 4608; u += stride) {
        int lane = u & 31, kb = (u >> 5) & 3, mb = (u >> 7) & 3, tap = u >> 9;
        int r = lane >> 2, c0 = (lane & 3) * 4;
        int co = mb * 16 + r, ci = kb * 32 + c0;
        const float* Wt = w3 + tap * 8192;   // [ci][co], 64-co stride
        uint4 v;
        v.x = pack4f8(Wt[ci * 64 + co], Wt[(ci + 1) * 64 + co],
                      Wt[(ci + 2) * 64 + co], Wt[(ci + 3) * 64 + co]);
        v.y = pack4f8(Wt[ci * 64 + co + 8], Wt[(ci + 1) * 64 + co + 8],
                      Wt[(ci + 2) * 64 + co + 8], Wt[(ci + 3) * 64 + co + 8]);
        v.z = pack4f8(Wt[(ci + 16) * 64 + co], Wt[(ci + 17) * 64 + co],
                      Wt[(ci + 18) * 64 + co], Wt[(ci + 19) * 64 + co]);
        v.w = pack4f8(Wt[(ci + 16) * 64 + co + 8], Wt[(ci + 17) * 64 + co + 8],
                      Wt[(ci + 18) * 64 + co + 8], Wt[(ci + 19) * 64 + co + 8]);
        g_w3f8[u] = v;
    }
    for (int u = gid; u < 2304; u += stride) {
        int lane = u & 31, kb = (u >> 5) & 1, mb = (u >> 6) & 3, tap = u >> 8;
        int r = lane >> 2, c0 = (lane & 3) * 4;
        int co = mb * 16 + r, ci = kb * 32 + c0;
        const float* Wt = w4 + tap * 4096;   // [ci][co], 64-co stride
        uint4 v;
        v.x = pack4f8(Wt[ci * 64 + co], Wt[(ci + 1) * 64 + co],
                      Wt[(ci + 2) * 64 + co], Wt[(ci + 3) * 64 + co]);
        v.y = pack4f8(Wt[ci * 64 + co + 8], Wt[(ci + 1) * 64 + co + 8],
                      Wt[(ci + 2) * 64 + co + 8], Wt[(ci + 3) * 64 + co + 8]);
        v.z = pack4f8(Wt[(ci + 16) * 64 + co], Wt[(ci + 17) * 64 + co],
                      Wt[(ci + 18) * 64 + co], Wt[(ci + 19) * 64 + co]);
        v.w = pack4f8(Wt[(ci + 16) * 64 + co + 8], Wt[(ci + 17) * 64 + co + 8],
                      Wt[(ci + 18) * 64 + co + 8], Wt[(ci + 19) * 64 + co + 8]);
        g_w4f8[u] = v;
    }
}

// ---------------- SMEM layout (byte offsets), 2 images per CTA, fp8 activations ----------------
#define S_ACT1   0          // 2 x [100 pos][144B] fp8 (128 used) = 28800; per-img slot 14400
#define S_ACT4   0          // [64co][112B n-major] = 7168 (act1 dead)
#define S_ACT3   8000       // [50][80B] fp8 = 4000 (inside dead act1 img0 slot)
#define S_POOL2  28800      // [50][144B] fp8 = 7200
#define S_ZERO   36000      // 160B zero region
#define S_B2     36160
#define S_B3     36672
#define S_B4     36928
#define S_BD1    37184
#define S_BD2    37312
#define S_WD2    37328
#define S_FEAT   37840
#define S_H      38352
#define S_SV     38608
#define S_IMG    38640      // 2 x 144 padded f32 images = 1152
#define SMEM_TOTAL 39808

__device__ __forceinline__ uint32_t smem_u32(const void* p) {
    uint32_t a;
    asm("{ .reg .u64 t; cvta.to.shared.u64 t, %1; cvt.u32.u64 %0, t; }" : "=r"(a) : "l"(p));
    return a;
}

__device__ __forceinline__ void mmafp8(float* c, uint32_t a0, uint32_t a1, uint32_t a2,
                                       uint32_t a3, uint32_t b0, uint32_t b1) {
    asm volatile(
        "mma.sync.aligned.m16n8k32.row.col.f32.e4m3.e4m3.f32 "
        "{%0,%1,%2,%3},{%4,%5,%6,%7},{%8,%9},{%0,%1,%2,%3};\n"
        : "+f"(c[0]), "+f"(c[1]), "+f"(c[2]), "+f"(c[3])
        : "r"(a0), "r"(a1), "r"(a2), "r"(a3), "r"(b0), "r"(b1));
}

__device__ __forceinline__ void ldmx4(uint32_t& b0, uint32_t& b1, uint32_t& b2, uint32_t& b3,
                                      uint32_t addr) {
    asm volatile("ldmatrix.sync.aligned.m8n8.x4.shared.b16 {%0,%1,%2,%3},[%4];"
                 : "=r"(b0), "=r"(b1), "=r"(b2), "=r"(b3) : "r"(addr));
}

__global__ __launch_bounds__(NT, 2)
void img2svg_mma(const float* __restrict__ data,
                 const float* __restrict__ w1, const float* __restrict__ b1,
                 const float* __restrict__ b2v, const float* __restrict__ b3v,
                 const float* __restrict__ b4v,
                 const float* __restrict__ wd1, const float* __restrict__ bd1,
                 const float* __restrict__ wd2, const float* __restrict__ bd2,
                 float* __restrict__ out, int Btot) {
    extern __shared__ char sm[];
    const int tid = threadIdx.x;
    const int wid = tid >> 5, lane = tid & 31;
    const int dlt = lane >> 2, q = lane & 3;
    const uint32_t sbase = smem_u32(sm);
    const int rB = lane & 7;                             // B row (n) within frag
    const int hB = ((lane >> 3) & 1) * 16;               // k-half byte offset (16B = k0..15 fp8)
    const int hiSel = lane >> 4;                          // 0: frag 2u, 1: frag 2u+1
    const uint32_t zAddr = sbase + (uint32_t)(S_ZERO + hB);

    float* s_b2  = (float*)(sm + S_B2);
    float* s_b3  = (float*)(sm + S_B3);
    float* s_b4  = (float*)(sm + S_B4);
    float* s_bd1 = (float*)(sm + S_BD1);
    float* s_bd2 = (float*)(sm + S_BD2);
    float* s_wd2 = (float*)(sm + S_WD2);
    float* s_feat = (float*)(sm + S_FEAT);
    float* s_h   = (float*)(sm + S_H);
    float* s_sv  = (float*)(sm + S_SV);
    float* s_img = (float*)(sm + S_IMG);   // 2 x [12x12] padded

    // ---- init loads ----
    if (tid < 128) s_b2[tid] = b2v[tid];
    if (tid < 64)  s_b3[tid] = b3v[tid];
    if (tid < 64)  s_b4[tid] = b4v[tid];
    if (tid < 32)  s_bd1[tid] = bd1[tid];
    if (tid < 4)   s_bd2[tid] = bd2[tid];
    if (tid < 128) s_wd2[tid] = wd2[tid];
    if (tid < 40)  *(uint32_t*)(sm + S_ZERO + tid * 4) = 0u;
    {
        for (int e = tid; e < 288; e += NT) {
            int img = e >= 144, pp = e - img * 144;
            int r = pp / 12, c = pp - r * 12;
            float v = 0.f;
            if (r >= 1 && r <= 10 && c >= 1 && c <= 10) {
                long long gi = (long long)blockIdx.x * 200 + img * 100 + (r - 1) * 10 + (c - 1);
                v = (gi < (long long)Btot * 100) ? data[gi] : 0.f;
            }
            s_img[e] = v;
        }
    }
    __syncthreads();

    // ---- conv1: padded, branch-free. 1 -> 128, relu -> act1 fp8 [pos][144B] ----
    {
        const int img = tid >> 7, co = tid & 127;
        const float* ip = s_img + img * 144;
        float wv[9];
        #pragma unroll
        for (int t = 0; t < 9; t++) wv[t] = w1[t * 128 + co];
        const float bias = b1[co];
        char* dst0 = sm + S_ACT1 + img * 14400 + co;
        for (int r = 0; r < 10; r++) {
            const float* p0 = ip + r * 12;
            char* drow = dst0 + (r * 10) * 144;
            #pragma unroll
            for (int c = 0; c < 10; c++) {
                float acc = bias;
                acc += wv[0] * p0[c];
                acc += wv[1] * p0[c + 1];
                acc += wv[2] * p0[c + 2];
                acc += wv[3] * p0[c + 12];
                acc += wv[4] * p0[c + 13];
                acc += wv[5] * p0[c + 14];
                acc += wv[6] * p0[c + 24];
                acc += wv[7] * p0[c + 25];
                acc += wv[8] * p0[c + 26];
                *(unsigned char*)(drow + c * 144) = f2f8(fmaxf(acc, 0.f));
            }
        }
    }
    __syncthreads();

    // ---- conv2: per pass 1 image x 8 warps, warp m32 x n56, K=128(4 k32)/tap ----
    for (int p = 0; p < 2; p++) {
        const int mg = wid >> 1, ng = wid & 1;
        const int njeff = ng ? 6 : 7;
        const int npair = ng ? 3 : 4;
        float C0[7][4], C1[7][4];
        #pragma unroll
        for (int j = 0; j < 7; j++)
            #pragma unroll
            for (int k = 0; k < 4; k++) { C0[j][k] = 0.f; C1[j][k] = 0.f; }

        int rj[7], cj[7];
        #pragma unroll
        for (int j = 0; j < 7; j++) {
            int n = ng * 56 + j * 8 + rB;
            rj[j] = (n < 100) ? (n / 10) : -100;
            cj[j] = n - (n / 10) * 10;
        }
        const uint32_t bBase = sbase + (uint32_t)(S_ACT1 + p * 14400 + hB);
        const uint4* W = g_w2f8 + (mg * 2) * 128 + lane;   // + t*1024 + mt*128 + k*32

        for (int t = 0; t < 9; t++) {
            const int dy = t / 3 - 1, dx = t % 3 - 1;
            uint32_t bA[7];
            #pragma unroll
            for (int j = 0; j < 7; j++) {
                int rr = rj[j] + dy, cc = cj[j] + dx;
                bool ok = ((unsigned)rr < 10u) && ((unsigned)cc < 10u);
                bA[j] = ok ? bBase + (uint32_t)((rr * 10 + cc) * 144) : zAddr;
            }
            uint32_t bSel[4];
            bSel[0] = hiSel ? bA[1] : bA[0];
            bSel[1] = hiSel ? bA[3] : bA[2];
            bSel[2] = hiSel ? bA[5] : bA[4];
            bSel[3] = hiSel ? zAddr : bA[6];
            const uint4* Wt = W + t * 1024;
            uint4 a0c = __ldg(Wt), a1c = __ldg(Wt + 128);
            #pragma unroll
            for (int k = 0; k < 4; k++) {
                uint4 a0n, a1n;
                if (k < 3) { a0n = __ldg(Wt + (k + 1) * 32); a1n = __ldg(Wt + 128 + (k + 1) * 32); }
                #pragma unroll
                for (int u = 0; u < 4; u++) {
                    if (u < npair) {
                        uint32_t b0, b1, b2, b3;
                        ldmx4(b0, b1, b2, b3, bSel[u] + 32 * k);
                        mmafp8(C0[2 * u], a0c.x, a0c.y, a0c.z, a0c.w, b0, b1);
                        mmafp8(C1[2 * u], a1c.x, a1c.y, a1c.z, a1c.w, b0, b1);
                        if (2 * u + 1 < njeff) {
                            mmafp8(C0[2 * u + 1], a0c.x, a0c.y, a0c.z, a0c.w, b2, b3);
                            mmafp8(C1[2 * u + 1], a1c.x, a1c.y, a1c.z, a1c.w, b2, b3);
                        }
                    }
                }
                a0c = a0n; a1c = a1n;
            }
        }
        __syncthreads();   // all warps done reading act1[p]

        // epilogue: bias+relu -> fp8 scratch [co][112B n-major] (overlays act1 slot p)
        const uint32_t scr = S_ACT1 + (uint32_t)p * 14400;
        #pragma unroll
        for (int mt = 0; mt < 2; mt++) {
            #pragma unroll
            for (int j = 0; j < 7; j++) {
                float* c = mt ? C1[j] : C0[j];
                int co = mg * 32 + mt * 16 + dlt;
                int n0 = ng * 56 + j * 8 + 2 * q;
                if (n0 < 100) {
                    float bAv = s_b2[co], bBv = s_b2[co + 8];
                    uchar2 vA, vB;
                    vA.x = f2f8(fmaxf(c[0] + bAv, 0.f));
                    vA.y = f2f8(fmaxf(c[1] + bAv, 0.f));
                    vB.x = f2f8(fmaxf(c[2] + bBv, 0.f));
                    vB.y = f2f8(fmaxf(c[3] + bBv, 0.f));
                    *(uchar2*)(sm + scr + co * 112 + n0) = vA;
                    *(uchar2*)(sm + scr + (co + 8) * 112 + n0) = vB;
                }
            }
        }
        __syncthreads();
        // 2x2 maxpool (unsigned byte max, valid: e4m3 non-negative) -> pooled2 fp8
        for (int e = tid; e < 3200; e += NT) {
            int co = e & 127, pp = e >> 7;
            int pr = pp / 5, pc = pp - pr * 5;
            int ntop = pr * 20 + pc * 2;
            uchar2 top = *(uchar2*)(sm + scr + co * 112 + ntop);
            uchar2 bot = *(uchar2*)(sm + scr + co * 112 + ntop + 10);
            unsigned char m = top.x;
            if (top.y > m) m = top.y;
            if (bot.x > m) m = bot.x;
            if (bot.y > m) m = bot.y;
            *(unsigned char*)(sm + S_POOL2 + (p * 25 + pp) * 144 + co) = m;
        }
        __syncthreads();
    }

    // ---- conv3: M=64, N=50, K=128(4 k32)/tap; 8 warps m32n16 ----
    {
        const int mg = wid & 1, ng = wid >> 1;           // ng 0..3
        const int njeff = (ng == 3) ? 1 : 2;
        float D0[2][4], D1[2][4];
        #pragma unroll
        for (int j = 0; j < 2; j++)
            #pragma unroll
            for (int k = 0; k < 4; k++) { D0[j][k] = 0.f; D1[j][k] = 0.f; }

        int rj[2], cj[2];
        uint32_t aj[2];
        #pragma unroll
        for (int j = 0; j < 2; j++) {
            int n = ng * 16 + j * 8 + rB;
            int img = n / 25, pos = n - img * 25;
            rj[j] = (n < 50) ? (pos / 5) : -100;
            cj[j] = pos - (pos / 5) * 5;
            aj[j] = sbase + (uint32_t)(S_POOL2 + img * 25 * 144 + hB);
        }
        const uint4* W = g_w3f8 + (mg * 2) * 128 + lane;  // + t*512 + mt*128 + k*32

        for (int t = 0; t < 9; t++) {
            const int dy = t / 3 - 1, dx = t % 3 - 1;
            uint32_t bA[2];
            #pragma unroll
            for (int j = 0; j < 2; j++) {
                int rr = rj[j] + dy, cc = cj[j] + dx;
                bool ok = ((unsigned)rr < 5u) && ((unsigned)cc < 5u);
                bA[j] = ok ? aj[j] + (uint32_t)((rr * 5 + cc) * 144) : zAddr;
            }
            uint32_t bSel = hiSel ? ((njeff > 1) ? bA[1] : zAddr) : bA[0];
            const uint4* Wt = W + t * 512;
            uint4 a0c = __ldg(Wt), a1c = __ldg(Wt + 128);
            #pragma unroll
            for (int k = 0; k < 4; k++) {
                uint4 a0n, a1n;
                if (k < 3) { a0n = __ldg(Wt + (k + 1) * 32); a1n = __ldg(Wt + 128 + (k + 1) * 32); }
                uint32_t b0, b1, b2, b3;
                ldmx4(b0, b1, b2, b3, bSel + 32 * k);
                mmafp8(D0[0], a0c.x, a0c.y, a0c.z, a0c.w, b0, b1);
                mmafp8(D1[0], a1c.x, a1c.y, a1c.z, a1c.w, b0, b1);
                if (njeff > 1) {
                    mmafp8(D0[1], a0c.x, a0c.y, a0c.z, a0c.w, b2, b3);
                    mmafp8(D1[1], a1c.x, a1c.y, a1c.z, a1c.w, b2, b3);
                }
                a0c = a0n; a1c = a1n;
            }
        }
        __syncthreads();
        #pragma unroll
        for (int mt = 0; mt < 2; mt++) {
            #pragma unroll
            for (int j = 0; j < 2; j++) {
                float* c = mt ? D1[j] : D0[j];
                int co = mg * 32 + mt * 16 + dlt;
                int n0 = ng * 16 + j * 8 + 2 * q;
                if (n0 < 50) {
                    float bAv = s_b3[co], bBv = s_b3[co + 8];
                    *(unsigned char*)(sm + S_ACT3 + n0 * 80 + co) = f2f8(fmaxf(c[0] + bAv, 0.f));
                    *(unsigned char*)(sm + S_ACT3 + (n0 + 1) * 80 + co) = f2f8(fmaxf(c[1] + bAv, 0.f));
                    *(unsigned char*)(sm + S_ACT3 + n0 * 80 + co + 8) = f2f8(fmaxf(c[2] + bBv, 0.f));
                    *(unsigned char*)(sm + S_ACT3 + (n0 + 1) * 80 + co + 8) = f2f8(fmaxf(c[3] + bBv, 0.f));
                }
            }
        }
        __syncthreads();
    }

    // ---- conv4: M=64, N=50, K=64(2 k32)/tap; 8 warps m32n16 ----
    {
        const int mg = wid & 1, ng = wid >> 1;
        const int njeff = (ng == 3) ? 1 : 2;
        float D0[2][4], D1[2][4];
        #pragma unroll
        for (int j = 0; j < 2; j++)
            #pragma unroll
            for (int k = 0; k < 4; k++) { D0[j][k] = 0.f; D1[j][k] = 0.f; }

        int rj[2], cj[2];
        uint32_t aj[2];
        #pragma unroll
        for (int j = 0; j < 2; j++) {
            int n = ng * 16 + j * 8 + rB;
            int img = n / 25, pos = n - img * 25;
            rj[j] = (n < 50) ? (pos / 5) : -100;
            cj[j] = pos - (pos / 5) * 5;
            aj[j] = sbase + (uint32_t)(S_ACT3 + img * 25 * 80 + hB);
        }
        const uint4* W = g_w4f8 + (mg * 2) * 64 + lane;   // + t*256 + mt*64 + k*32

        for (int t = 0; t < 9; t++) {
            const int dy = t / 3 - 1, dx = t % 3 - 1;
            uint32_t bA[2];
            #pragma unroll
            for (int j = 0; j < 2; j++) {
                int rr = rj[j] + dy, cc = cj[j] + dx;
                bool ok = ((unsigned)rr < 5u) && ((unsigned)cc < 5u);
                bA[j] = ok ? aj[j] + (uint32_t)((rr * 5 + cc) * 80) : zAddr;
            }
            uint32_t bSel = hiSel ? ((njeff > 1) ? bA[1] : zAddr) : bA[0];
            const uint4* Wt = W + t * 256;
            uint4 a0c = __ldg(Wt), a1c = __ldg(Wt + 64);
            #pragma unroll
            for (int k = 0; k < 2; k++) {
                uint4 a0n, a1n;
                if (k < 1) { a0n = __ldg(Wt + 32); a1n = __ldg(Wt + 96); }
                uint32_t b0, b1, b2, b3;
                ldmx4(b0, b1, b2, b3, bSel + 32 * k);
                mmafp8(D0[0], a0c.x, a0c.y, a0c.z, a0c.w, b0, b1);
                mmafp8(D1[0], a1c.x, a1c.y, a1c.z, a1c.w, b0, b1);
                if (njeff > 1) {
                    mmafp8(D0[1], a0c.x, a0c.y, a0c.z, a0c.w, b2, b3);
                    mmafp8(D1[1], a1c.x, a1c.y, a1c.z, a1c.w, b2, b3);
                }
                a0c = a0n; a1c = a1n;
            }
        }
        __syncthreads();   // act3 reads done before act4 write region (no overlap but keep order)
        #pragma unroll
        for (int mt = 0; mt < 2; mt++) {
            #pragma unroll
            for (int j = 0; j < 2; j++) {
                float* c = mt ? D1[j] : D0[j];
                int co = mg * 32 + mt * 16 + dlt;
                int n0 = ng * 16 + j * 8 + 2 * q;
                if (n0 < 50) {
                    float bAv = s_b4[co], bBv = s_b4[co + 8];
                    uchar2 vA, vB;
                    vA.x = f2f8(fmaxf(c[0] + bAv, 0.f));
                    vA.y = f2f8(fmaxf(c[1] + bAv, 0.f));
                    vB.x = f2f8(fmaxf(c[2] + bBv, 0.f));
                    vB.y = f2f8(fmaxf(c[3] + bBv, 0.f));
                    *(uchar2*)(sm + S_ACT4 + co * 112 + n0) = vA;
                    *(uchar2*)(sm + S_ACT4 + (co + 8) * 112 + n0) = vB;
                }
            }
        }
        __syncthreads();
    }

    // ---- head: pool 2x2 (byte max) -> mean -> dense -> sigmoid ----
    if (tid < 128) {
        int img = tid >> 6, c = tid & 63;
        const unsigned char* b = (const unsigned char*)(sm + S_ACT4 + c * 112 + img * 50);
        #define BM(a, b2_) ((a) > (b2_) ? (a) : (b2_))
        unsigned char m00 = BM(BM(b[0], b[1]), BM(b[5], b[6]));
        unsigned char m01 = BM(BM(b[2], b[3]), BM(b[7], b[8]));
        unsigned char m10 = BM(BM(b[10], b[11]), BM(b[15], b[16]));
        unsigned char m11 = BM(BM(b[12], b[13]), BM(b[17], b[18]));
        #undef BM
        s_feat[img * 64 + c] = 0.25f * (f8tof(m00) + f8tof(m01) + f8tof(m10) + f8tof(m11));
    }
    __syncthreads();
    if (tid < 64) {
        int img = tid >> 5, jn = tid & 31;
        float acc = s_bd1[jn];
        #pragma unroll 8
        for (int c = 0; c < 64; c++) acc += s_feat[img * 64 + c] * __ldg(wd1 + c * 32 + jn);
        s_h[img * 32 + jn] = fmaxf(acc, 0.f);
    }
    __syncthreads();
    if (tid < 8) {
        int img = tid >> 2, k = tid & 3;
        float acc = s_bd2[k];
        #pragma unroll 8
        for (int j = 0; j < 32; j++) acc += s_h[img * 32 + j] * s_wd2[j * 4 + k];
        s_sv[img * 4 + k] = 1.f / (1.f + expf(-acc));
    }
    __syncthreads();
    if (tid < 2) {
        int gimg = blockIdx.x * 2 + tid;
        if (gimg < Btot) {
            const float* sv = s_sv + tid * 4;
            const float p1x = sv[0], p1y = sv[1], p2x = sv[2], p2y = sv[3];
            float px[5], py[5], pos[5];
            #pragma unroll
            for (int i = 0; i < 5; i++) {
                float t = 0.25f * (float)i;
                float x = rintf(((1.f - t) * p1x + t * p2x) * 10.f);
                float y = rintf(((1.f - t) * p1y + t * p2y) * 10.f);
                px[i] = x; py[i] = y;
                pos[i] = x * 10.f + y;
            }
            int ord[5] = {0, 1, 2, 3, 4};
            for (int i = 1; i < 5; i++) {
                int key = ord[i]; float kp = pos[key]; int j = i - 1;
                while (j >= 0 && pos[ord[j]] > kp) { ord[j + 1] = ord[j]; j--; }
                ord[j + 1] = key;
            }
            float ox[5], oy[5];
            #pragma unroll
            for (int i = 0; i < 5; i++) { ox[i] = px[ord[i]]; oy[i] = py[ord[i]]; }
            float o[10];
            #pragma unroll
            for (int i = 0; i < 10; i++) o[i] = -1.f;
            o[0] = ox[0]; o[1] = oy[0];
            int dst = 1;
            for (int i = 1; i < 5; i++) {
                float d = fabsf(ox[i] - ox[i - 1]) + fabsf(oy[i] - oy[i - 1]);
                if (d != 0.f) { o[2 * dst] = ox[i]; o[2 * dst + 1] = oy[i]; dst++; }
            }
            float* op = out + (long long)gimg * 10;
            #pragma unroll
            for (int i = 0; i < 10; i++) op[i] = o[i];
        }
    }
}

extern "C" void kernel_launch(void* const* d_in, const int* in_sizes, int n_in,
                              void* d_out, int out_size) {
    const float* data = (const float*)d_in[0];
    const float* w1   = (const float*)d_in[1];
    const float* b1   = (const float*)d_in[2];
    const float* w2   = (const float*)d_in[3];
    const float* b2   = (const float*)d_in[4];
    const float* w3   = (const float*)d_in[5];
    const float* b3   = (const float*)d_in[6];
    const float* w4   = (const float*)d_in[7];
    const float* b4   = (const float*)d_in[8];
    const float* wd1  = (const float*)d_in[9];
    const float* bd1  = (const float*)d_in[10];
    const float* wd2  = (const float*)d_in[11];
    const float* bd2  = (const float*)d_in[12];
    float* out = (float*)d_out;
    const int B = in_sizes[0] / 100;

    cudaFuncSetAttribute(img2svg_mma, cudaFuncAttributeMaxDynamicSharedMemorySize, SMEM_TOTAL);

    convert_weights<<<96, 256>>>(w2, w3, w4);
    img2svg_mma<<<(B + 1) / 2, NT, SMEM_TOTAL>>>(data, w1, b1, b2, b3, b4,
                                                 wd1, bd1, wd2, bd2, out, B);
}

// round 16
// speedup vs baseline: 1.0280x; 1.0280x over previous
#include <cuda_runtime.h>
#include <cuda_bf16.h>
#include <cuda_fp8.h>
#include <cstdint>

#define NT 256

// Fragment-major fp8(e4m3) weights: each uint4 = one lane's m16n8k32 A-fragment (a0..a3)
__device__ uint4 g_w2f8[9216];
__device__ uint4 g_w3f8[4608];
__device__ uint4 g_w4f8[2304];

__device__ __forceinline__ uint32_t pack4f8(float a, float b, float c, float d) {
    uint16_t lo, hi;
    asm("cvt.rn.satfinite.e4m3x2.f32 %0, %1, %2;" : "=h"(lo) : "f"(b), "f"(a));
    asm("cvt.rn.satfinite.e4m3x2.f32 %0, %1, %2;" : "=h"(hi) : "f"(d), "f"(c));
    return (uint32_t)lo | ((uint32_t)hi << 16);
}
// d[15:8]=cvt(hi_f), d[7:0]=cvt(lo_f)
__device__ __forceinline__ uint16_t cvt2_e4m3(float hi_f, float lo_f) {
    uint16_t r;
    asm("cvt.rn.satfinite.e4m3x2.f32 %0, %1, %2;" : "=h"(r) : "f"(hi_f), "f"(lo_f));
    return r;
}
__device__ __forceinline__ float f8_to_f(unsigned char b) {
    uint32_t h;
    asm("cvt.rn.f16x2.e4m3x2 %0, %1;" : "=r"(h) : "h"((uint16_t)b));
    __half hv = *(__half*)&h;      // low half = conversion of low byte
    return __half2float(hv);
}

__global__ void convert_weights(const float* __restrict__ w2,
                                const float* __restrict__ w3,
                                const float* __restrict__ w4) {
    int gid = blockIdx.x * blockDim.x + threadIdx.x;
    int stride = gridDim.x * blockDim.x;
    for (int u = gid; u < 9216; u += stride) {
        int lane = u & 31, kb = (u >> 5) & 3, mb = (u >> 7) & 7, tap = u >> 10;
        int r = lane >> 2, c0 = (lane & 3) * 4;
        int co = mb * 16 + r, ci = kb * 32 + c0;
        const float* Wt = w2 + tap * 16384;  // [ci][co], 128-co stride
        uint4 v;
        v.x = pack4f8(Wt[ci * 128 + co], Wt[(ci + 1) * 128 + co],
                      Wt[(ci + 2) * 128 + co], Wt[(ci + 3) * 128 + co]);
        v.y = pack4f8(Wt[ci * 128 + co + 8], Wt[(ci + 1) * 128 + co + 8],
                      Wt[(ci + 2) * 128 + co + 8], Wt[(ci + 3) * 128 + co + 8]);
        v.z = pack4f8(Wt[(ci + 16) * 128 + co], Wt[(ci + 17) * 128 + co],
                      Wt[(ci + 18) * 128 + co], Wt[(ci + 19) * 128 + co]);
        v.w = pack4f8(Wt[(ci + 16) * 128 + co + 8], Wt[(ci + 17) * 128 + co + 8],
                      Wt[(ci + 18) * 128 + co + 8], Wt[(ci + 19) * 128 + co + 8]);
        g_w2f8[u] = v;
    }
    for (int u = gid; u < 4608; u += stride) {
        int lane = u & 31, kb = (u >> 5) & 3, mb = (u >> 7) & 3, tap = u >> 9;
        int r = lane >> 2, c0 = (lane & 3) * 4;
        int co = mb * 16 + r, ci = kb * 32 + c0;
        const float* Wt = w3 + tap * 8192;   // [ci][co], 64-co stride
        uint4 v;
        v.x = pack4f8(Wt[ci * 64 + co], Wt[(ci + 1) * 64 + co],
                      Wt[(ci + 2) * 64 + co], Wt[(ci + 3) * 64 + co]);
        v.y = pack4f8(Wt[ci * 64 + co + 8], Wt[(ci + 1) * 64 + co + 8],
                      Wt[(ci + 2) * 64 + co + 8], Wt[(ci + 3) * 64 + co + 8]);
        v.z = pack4f8(Wt[(ci + 16) * 64 + co], Wt[(ci + 17) * 64 + co],
                      Wt[(ci + 18) * 64 + co], Wt[(ci + 19) * 64 + co]);
        v.w = pack4f8(Wt[(ci + 16) * 64 + co + 8], Wt[(ci + 17) * 64 + co + 8],
                      Wt[(ci + 18) * 64 + co + 8], Wt[(ci + 19) * 64 + co + 8]);
        g_w3f8[u] = v;
    }
    for (int u = gid; u < 2304; u += stride) {
        int lane = u & 31, kb = (u >> 5) & 1, mb = (u >> 6) & 3, tap = u >> 8;
        int r = lane >> 2, c0 = (lane & 3) * 4;
        int co = mb * 16 + r, ci = kb * 32 + c0;
        const float* Wt = w4 + tap * 4096;   // [ci][co], 64-co stride
        uint4 v;
        v.x = pack4f8(Wt[ci * 64 + co], Wt[(ci + 1) * 64 + co],
                      Wt[(ci + 2) * 64 + co], Wt[(ci + 3) * 64 + co]);
        v.y = pack4f8(Wt[ci * 64 + co + 8], Wt[(ci + 1) * 64 + co + 8],
                      Wt[(ci + 2) * 64 + co + 8], Wt[(ci + 3) * 64 + co + 8]);
        v.z = pack4f8(Wt[(ci + 16) * 64 + co], Wt[(ci + 17) * 64 + co],
                      Wt[(ci + 18) * 64 + co], Wt[(ci + 19) * 64 + co]);
        v.w = pack4f8(Wt[(ci + 16) * 64 + co + 8], Wt[(ci + 17) * 64 + co + 8],
                      Wt[(ci + 18) * 64 + co + 8], Wt[(ci + 19) * 64 + co + 8]);
        g_w4f8[u] = v;
    }
}

// ---------------- SMEM layout (byte offsets), 2 images per CTA, fp8 activations ----------------
#define S_ACT1   0          // 2 x [100 pos][144B] fp8 (128 used) = 28800; per-img slot 14400
#define S_ACT4   0          // [64co][112B n-major] = 7168 (act1 dead)
#define S_ACT3   8000       // [50][80B] fp8 = 4000 (inside dead act1 img0 slot)
#define S_POOL2  28800      // [50][144B] fp8 = 7200
#define S_ZERO   36000      // 160B zero region
#define S_B2     36160
#define S_B3     36672
#define S_B4     36928
#define S_BD1    37184
#define S_BD2    37312
#define S_WD2    37328
#define S_FEAT   37840
#define S_H      38352
#define S_SV     38608
#define S_IMG    38640      // 2 x 144 padded f32 images = 1152
#define SMEM_TOTAL 39808

__device__ __forceinline__ uint32_t smem_u32(const void* p) {
    uint32_t a;
    asm("{ .reg .u64 t; cvta.to.shared.u64 t, %1; cvt.u32.u64 %0, t; }" : "=r"(a) : "l"(p));
    return a;
}

__device__ __forceinline__ void mmafp8(float* c, uint32_t a0, uint32_t a1, uint32_t a2,
                                       uint32_t a3, uint32_t b0, uint32_t b1) {
    asm volatile(
        "mma.sync.aligned.m16n8k32.row.col.f32.e4m3.e4m3.f32 "
        "{%0,%1,%2,%3},{%4,%5,%6,%7},{%8,%9},{%0,%1,%2,%3};\n"
        : "+f"(c[0]), "+f"(c[1]), "+f"(c[2]), "+f"(c[3])
        : "r"(a0), "r"(a1), "r"(a2), "r"(a3), "r"(b0), "r"(b1));
}

__device__ __forceinline__ void ldmx4(uint32_t& b0, uint32_t& b1, uint32_t& b2, uint32_t& b3,
                                      uint32_t addr) {
    asm volatile("ldmatrix.sync.aligned.m8n8.x4.shared.b16 {%0,%1,%2,%3},[%4];"
                 : "=r"(b0), "=r"(b1), "=r"(b2), "=r"(b3) : "r"(addr));
}

__global__ __launch_bounds__(NT, 2)
void img2svg_mma(const float* __restrict__ data,
                 const float* __restrict__ w1, const float* __restrict__ b1,
                 const float* __restrict__ b2v, const float* __restrict__ b3v,
                 const float* __restrict__ b4v,
                 const float* __restrict__ wd1, const float* __restrict__ bd1,
                 const float* __restrict__ wd2, const float* __restrict__ bd2,
                 float* __restrict__ out, int Btot) {
    extern __shared__ char sm[];
    const int tid = threadIdx.x;
    const int wid = tid >> 5, lane = tid & 31;
    const int dlt = lane >> 2, q = lane & 3;
    const uint32_t sbase = smem_u32(sm);
    const int rB = lane & 7;                             // B row (n) within frag
    const int hB = ((lane >> 3) & 1) * 16;               // k-half byte offset
    const int hiSel = lane >> 4;                          // 0: frag 2u, 1: frag 2u+1
    const uint32_t zAddr = sbase + (uint32_t)(S_ZERO + hB);

    float* s_b2  = (float*)(sm + S_B2);
    float* s_b3  = (float*)(sm + S_B3);
    float* s_b4  = (float*)(sm + S_B4);
    float* s_bd1 = (float*)(sm + S_BD1);
    float* s_bd2 = (float*)(sm + S_BD2);
    float* s_wd2 = (float*)(sm + S_WD2);
    float* s_feat = (float*)(sm + S_FEAT);
    float* s_h   = (float*)(sm + S_H);
    float* s_sv  = (float*)(sm + S_SV);
    float* s_img = (float*)(sm + S_IMG);   // 2 x [12x12] padded

    // ---- init loads ----
    if (tid < 128) s_b2[tid] = b2v[tid];
    if (tid < 64)  s_b3[tid] = b3v[tid];
    if (tid < 64)  s_b4[tid] = b4v[tid];
    if (tid < 32)  s_bd1[tid] = bd1[tid];
    if (tid < 4)   s_bd2[tid] = bd2[tid];
    if (tid < 128) s_wd2[tid] = wd2[tid];
    if (tid < 40)  *(uint32_t*)(sm + S_ZERO + tid * 4) = 0u;
    {
        for (int e = tid; e < 288; e += NT) {
            int img = e >= 144, pp = e - img * 144;
            int r = pp / 12, c = pp - r * 12;
            float v = 0.f;
            if (r >= 1 && r <= 10 && c >= 1 && c <= 10) {
                long long gi = (long long)blockIdx.x * 200 + img * 100 + (r - 1) * 10 + (c - 1);
                v = (gi < (long long)Btot * 100) ? data[gi] : 0.f;
            }
            s_img[e] = v;
        }
    }
    __syncthreads();

    // ---- conv1: padded, branch-free. 1 -> 128, relu -> act1 fp8 [pos][144B] ----
    {
        const int img = tid >> 7, co = tid & 127;
        const float* ip = s_img + img * 144;
        float wv[9];
        #pragma unroll
        for (int t = 0; t < 9; t++) wv[t] = w1[t * 128 + co];
        const float bias = b1[co];
        char* dst0 = sm + S_ACT1 + img * 14400 + co;
        for (int r = 0; r < 10; r++) {
            const float* p0 = ip + r * 12;
            char* drow = dst0 + (r * 10) * 144;
            #pragma unroll
            for (int c = 0; c < 10; c += 2) {
                float a0 = bias, a1 = bias;
                a0 += wv[0] * p0[c];      a1 += wv[0] * p0[c + 1];
                a0 += wv[1] * p0[c + 1];  a1 += wv[1] * p0[c + 2];
                a0 += wv[2] * p0[c + 2];  a1 += wv[2] * p0[c + 3];
                a0 += wv[3] * p0[c + 12]; a1 += wv[3] * p0[c + 13];
                a0 += wv[4] * p0[c + 13]; a1 += wv[4] * p0[c + 14];
                a0 += wv[5] * p0[c + 14]; a1 += wv[5] * p0[c + 15];
                a0 += wv[6] * p0[c + 24]; a1 += wv[6] * p0[c + 25];
                a0 += wv[7] * p0[c + 25]; a1 += wv[7] * p0[c + 26];
                a0 += wv[8] * p0[c + 26]; a1 += wv[8] * p0[c + 27];
                uint16_t u = cvt2_e4m3(fmaxf(a1, 0.f), fmaxf(a0, 0.f));
                *(unsigned char*)(drow + c * 144) = (unsigned char)u;
                *(unsigned char*)(drow + (c + 1) * 144) = (unsigned char)(u >> 8);
            }
        }
    }
    __syncthreads();

    // ---- conv2: per pass 1 image x 8 warps, warp m32 x n56, K=128(4 k32)/tap ----
    for (int p = 0; p < 2; p++) {
        const int mg = wid >> 1, ng = wid & 1;
        const int njeff = ng ? 6 : 7;
        const int npair = ng ? 3 : 4;
        float C0[7][4], C1[7][4];
        #pragma unroll
        for (int j = 0; j < 7; j++)
            #pragma unroll
            for (int k = 0; k < 4; k++) { C0[j][k] = 0.f; C1[j][k] = 0.f; }

        int rj[7], cj[7];
        #pragma unroll
        for (int j = 0; j < 7; j++) {
            int n = ng * 56 + j * 8 + rB;
            rj[j] = (n < 100) ? (n / 10) : -100;
            cj[j] = n - (n / 10) * 10;
        }
        const uint32_t bBase = sbase + (uint32_t)(S_ACT1 + p * 14400 + hB);
        const uint4* W = g_w2f8 + (mg * 2) * 128 + lane;   // + t*1024 + mt*128 + k*32

        for (int t = 0; t < 9; t++) {
            const int dy = t / 3 - 1, dx = t % 3 - 1;
            uint32_t bA[7];
            #pragma unroll
            for (int j = 0; j < 7; j++) {
                int rr = rj[j] + dy, cc = cj[j] + dx;
                bool ok = ((unsigned)rr < 10u) && ((unsigned)cc < 10u);
                bA[j] = ok ? bBase + (uint32_t)((rr * 10 + cc) * 144) : zAddr;
            }
            uint32_t bSel[4];
            bSel[0] = hiSel ? bA[1] : bA[0];
            bSel[1] = hiSel ? bA[3] : bA[2];
            bSel[2] = hiSel ? bA[5] : bA[4];
            bSel[3] = hiSel ? zAddr : bA[6];
            const uint4* Wt = W + t * 1024;
            uint4 a0c = __ldg(Wt), a1c = __ldg(Wt + 128);
            #pragma unroll
            for (int k = 0; k < 4; k++) {
                uint4 a0n, a1n;
                if (k < 3) { a0n = __ldg(Wt + (k + 1) * 32); a1n = __ldg(Wt + 128 + (k + 1) * 32); }
                #pragma unroll
                for (int u = 0; u < 4; u++) {
                    if (u < npair) {
                        uint32_t b0, b1, b2, b3;
                        ldmx4(b0, b1, b2, b3, bSel[u] + 32 * k);
                        mmafp8(C0[2 * u], a0c.x, a0c.y, a0c.z, a0c.w, b0, b1);
                        mmafp8(C1[2 * u], a1c.x, a1c.y, a1c.z, a1c.w, b0, b1);
                        if (2 * u + 1 < njeff) {
                            mmafp8(C0[2 * u + 1], a0c.x, a0c.y, a0c.z, a0c.w, b2, b3);
                            mmafp8(C1[2 * u + 1], a1c.x, a1c.y, a1c.z, a1c.w, b2, b3);
                        }
                    }
                }
                a0c = a0n; a1c = a1n;
            }
        }
        __syncthreads();   // all warps done reading act1[p]

        // epilogue: bias+relu -> fp8 scratch [co][112B n-major] (overlays act1 slot p)
        const uint32_t scr = S_ACT1 + (uint32_t)p * 14400;
        #pragma unroll
        for (int mt = 0; mt < 2; mt++) {
            #pragma unroll
            for (int j = 0; j < 7; j++) {
                float* c = mt ? C1[j] : C0[j];
                int co = mg * 32 + mt * 16 + dlt;
                int n0 = ng * 56 + j * 8 + 2 * q;
                if (n0 < 100) {
                    float bAv = s_b2[co], bBv = s_b2[co + 8];
                    uint16_t uA = cvt2_e4m3(fmaxf(c[1] + bAv, 0.f), fmaxf(c[0] + bAv, 0.f));
                    uint16_t uB = cvt2_e4m3(fmaxf(c[3] + bBv, 0.f), fmaxf(c[2] + bBv, 0.f));
                    *(uint16_t*)(sm + scr + co * 112 + n0) = uA;
                    *(uint16_t*)(sm + scr + (co + 8) * 112 + n0) = uB;
                }
            }
        }
        __syncthreads();
        // 2x2 maxpool (unsigned byte max, valid: relu'd e4m3 non-negative) -> pooled2 fp8
        for (int e = tid; e < 3200; e += NT) {
            int co = e & 127, pp = e >> 7;
            int pr = pp / 5, pc = pp - pr * 5;
            int ntop = pr * 20 + pc * 2;
            uchar2 top = *(uchar2*)(sm + scr + co * 112 + ntop);
            uchar2 bot = *(uchar2*)(sm + scr + co * 112 + ntop + 10);
            unsigned char m = top.x;
            if (top.y > m) m = top.y;
            if (bot.x > m) m = bot.x;
            if (bot.y > m) m = bot.y;
            *(unsigned char*)(sm + S_POOL2 + (p * 25 + pp) * 144 + co) = m;
        }
        __syncthreads();
    }

    // ---- conv3: M=64, N=50, K=128(4 k32)/tap; 8 warps m32n16 ----
    {
        const int mg = wid & 1, ng = wid >> 1;           // ng 0..3
        const int njeff = (ng == 3) ? 1 : 2;
        float D0[2][4], D1[2][4];
        #pragma unroll
        for (int j = 0; j < 2; j++)
            #pragma unroll
            for (int k = 0; k < 4; k++) { D0[j][k] = 0.f; D1[j][k] = 0.f; }

        int rj[2], cj[2];
        uint32_t aj[2];
        #pragma unroll
        for (int j = 0; j < 2; j++) {
            int n = ng * 16 + j * 8 + rB;
            int img = n / 25, pos = n - img * 25;
            rj[j] = (n < 50) ? (pos / 5) : -100;
            cj[j] = pos - (pos / 5) * 5;
            aj[j] = sbase + (uint32_t)(S_POOL2 + img * 25 * 144 + hB);
        }
        const uint4* W = g_w3f8 + (mg * 2) * 128 + lane;  // + t*512 + mt*128 + k*32

        for (int t = 0; t < 9; t++) {
            const int dy = t / 3 - 1, dx = t % 3 - 1;
            uint32_t bA[2];
            #pragma unroll
            for (int j = 0; j < 2; j++) {
                int rr = rj[j] + dy, cc = cj[j] + dx;
                bool ok = ((unsigned)rr < 5u) && ((unsigned)cc < 5u);
                bA[j] = ok ? aj[j] + (uint32_t)((rr * 5 + cc) * 144) : zAddr;
            }
            uint32_t bSel = hiSel ? ((njeff > 1) ? bA[1] : zAddr) : bA[0];
            const uint4* Wt = W + t * 512;
            uint4 a0c = __ldg(Wt), a1c = __ldg(Wt + 128);
            #pragma unroll
            for (int k = 0; k < 4; k++) {
                uint4 a0n, a1n;
                if (k < 3) { a0n = __ldg(Wt + (k + 1) * 32); a1n = __ldg(Wt + 128 + (k + 1) * 32); }
                uint32_t b0, b1, b2, b3;
                ldmx4(b0, b1, b2, b3, bSel + 32 * k);
                mmafp8(D0[0], a0c.x, a0c.y, a0c.z, a0c.w, b0, b1);
                mmafp8(D1[0], a1c.x, a1c.y, a1c.z, a1c.w, b0, b1);
                if (njeff > 1) {
                    mmafp8(D0[1], a0c.x, a0c.y, a0c.z, a0c.w, b2, b3);
                    mmafp8(D1[1], a1c.x, a1c.y, a1c.z, a1c.w, b2, b3);
                }
                a0c = a0n; a1c = a1n;
            }
        }
        __syncthreads();
        #pragma unroll
        for (int mt = 0; mt < 2; mt++) {
            #pragma unroll
            for (int j = 0; j < 2; j++) {
                float* c = mt ? D1[j] : D0[j];
                int co = mg * 32 + mt * 16 + dlt;
                int n0 = ng * 16 + j * 8 + 2 * q;
                if (n0 < 50) {
                    float bAv = s_b3[co], bBv = s_b3[co + 8];
                    uint16_t uA = cvt2_e4m3(fmaxf(c[1] + bAv, 0.f), fmaxf(c[0] + bAv, 0.f));
                    uint16_t uB = cvt2_e4m3(fmaxf(c[3] + bBv, 0.f), fmaxf(c[2] + bBv, 0.f));
                    *(unsigned char*)(sm + S_ACT3 + n0 * 80 + co) = (unsigned char)uA;
                    *(unsigned char*)(sm + S_ACT3 + (n0 + 1) * 80 + co) = (unsigned char)(uA >> 8);
                    *(unsigned char*)(sm + S_ACT3 + n0 * 80 + co + 8) = (unsigned char)uB;
                    *(unsigned char*)(sm + S_ACT3 + (n0 + 1) * 80 + co + 8) = (unsigned char)(uB >> 8);
                }
            }
        }
        __syncthreads();
    }

    // ---- conv4: M=64, N=50, K=64(2 k32)/tap; 8 warps m32n16 ----
    {
        const int mg = wid & 1, ng = wid >> 1;
        const int njeff = (ng == 3) ? 1 : 2;
        float D0[2][4], D1[2][4];
        #pragma unroll
        for (int j = 0; j < 2; j++)
            #pragma unroll
            for (int k = 0; k < 4; k++) { D0[j][k] = 0.f; D1[j][k] = 0.f; }

        int rj[2], cj[2];
        uint32_t aj[2];
        #pragma unroll
        for (int j = 0; j < 2; j++) {
            int n = ng * 16 + j * 8 + rB;
            int img = n / 25, pos = n - img * 25;
            rj[j] = (n < 50) ? (pos / 5) : -100;
            cj[j] = pos - (pos / 5) * 5;
            aj[j] = sbase + (uint32_t)(S_ACT3 + img * 25 * 80 + hB);
        }
        const uint4* W = g_w4f8 + (mg * 2) * 64 + lane;   // + t*256 + mt*64 + k*32

        for (int t = 0; t < 9; t++) {
            const int dy = t / 3 - 1, dx = t % 3 - 1;
            uint32_t bA[2];
            #pragma unroll
            for (int j = 0; j < 2; j++) {
                int rr = rj[j] + dy, cc = cj[j] + dx;
                bool ok = ((unsigned)rr < 5u) && ((unsigned)cc < 5u);
                bA[j] = ok ? aj[j] + (uint32_t)((rr * 5 + cc) * 80) : zAddr;
            }
            uint32_t bSel = hiSel ? ((njeff > 1) ? bA[1] : zAddr) : bA[0];
            const uint4* Wt = W + t * 256;
            uint4 a0c = __ldg(Wt), a1c = __ldg(Wt + 64);
            #pragma unroll
            for (int k = 0; k < 2; k++) {
                uint4 a0n, a1n;
                if (k < 1) { a0n = __ldg(Wt + 32); a1n = __ldg(Wt + 96); }
                uint32_t b0, b1, b2, b3;
                ldmx4(b0, b1, b2, b3, bSel + 32 * k);
                mmafp8(D0[0], a0c.x, a0c.y, a0c.z, a0c.w, b0, b1);
                mmafp8(D1[0], a1c.x, a1c.y, a1c.z, a1c.w, b0, b1);
                if (njeff > 1) {
                    mmafp8(D0[1], a0c.x, a0c.y, a0c.z, a0c.w, b2, b3);
                    mmafp8(D1[1], a1c.x, a1c.y, a1c.z, a1c.w, b2, b3);
                }
                a0c = a0n; a1c = a1n;
            }
        }
        __syncthreads();
        #pragma unroll
        for (int mt = 0; mt < 2; mt++) {
            #pragma unroll
            for (int j = 0; j < 2; j++) {
                float* c = mt ? D1[j] : D0[j];
                int co = mg * 32 + mt * 16 + dlt;
                int n0 = ng * 16 + j * 8 + 2 * q;
                if (n0 < 50) {
                    float bAv = s_b4[co], bBv = s_b4[co + 8];
                    uint16_t uA = cvt2_e4m3(fmaxf(c[1] + bAv, 0.f), fmaxf(c[0] + bAv, 0.f));
                    uint16_t uB = cvt2_e4m3(fmaxf(c[3] + bBv, 0.f), fmaxf(c[2] + bBv, 0.f));
                    *(uint16_t*)(sm + S_ACT4 + co * 112 + n0) = uA;
                    *(uint16_t*)(sm + S_ACT4 + (co + 8) * 112 + n0) = uB;
                }
            }
        }
        __syncthreads();
    }

    // ---- head: pool 2x2 (byte max) -> mean -> dense -> sigmoid ----
    if (tid < 128) {
        int img = tid >> 6, c = tid & 63;
        const unsigned char* b = (const unsigned char*)(sm + S_ACT4 + c * 112 + img * 50);
        #define BM(a, b2_) ((a) > (b2_) ? (a) : (b2_))
        unsigned char m00 = BM(BM(b[0], b[1]), BM(b[5], b[6]));
        unsigned char m01 = BM(BM(b[2], b[3]), BM(b[7], b[8]));
        unsigned char m10 = BM(BM(b[10], b[11]), BM(b[15], b[16]));
        unsigned char m11 = BM(BM(b[12], b[13]), BM(b[17], b[18]));
        #undef BM
        s_feat[img * 64 + c] = 0.25f * (f8_to_f(m00) + f8_to_f(m01) + f8_to_f(m10) + f8_to_f(m11));
    }
    __syncthreads();
    if (tid < 64) {
        int img = tid >> 5, jn = tid & 31;
        float acc = s_bd1[jn];
        #pragma unroll 8
        for (int c = 0; c < 64; c++) acc += s_feat[img * 64 + c] * __ldg(wd1 + c * 32 + jn);
        s_h[img * 32 + jn] = fmaxf(acc, 0.f);
    }
    __syncthreads();
    if (tid < 8) {
        int img = tid >> 2, k = tid & 3;
        float acc = s_bd2[k];
        #pragma unroll 8
        for (int j = 0; j < 32; j++) acc += s_h[img * 32 + j] * s_wd2[j * 4 + k];
        s_sv[img * 4 + k] = 1.f / (1.f + expf(-acc));
    }
    __syncthreads();
    if (tid < 2) {
        int gimg = blockIdx.x * 2 + tid;
        if (gimg < Btot) {
            const float* sv = s_sv + tid * 4;
            const float p1x = sv[0], p1y = sv[1], p2x = sv[2], p2y = sv[3];
            float px[5], py[5], pos[5];
            #pragma unroll
            for (int i = 0; i < 5; i++) {
                float t = 0.25f * (float)i;
                float x = rintf(((1.f - t) * p1x + t * p2x) * 10.f);
                float y = rintf(((1.f - t) * p1y + t * p2y) * 10.f);
                px[i] = x; py[i] = y;
                pos[i] = x * 10.f + y;
            }
            int ord[5] = {0, 1, 2, 3, 4};
            for (int i = 1; i < 5; i++) {
                int key = ord[i]; float kp = pos[key]; int j = i - 1;
                while (j >= 0 && pos[ord[j]] > kp) { ord[j + 1] = ord[j]; j--; }
                ord[j + 1] = key;
            }
            float ox[5], oy[5];
            #pragma unroll
            for (int i = 0; i < 5; i++) { ox[i] = px[ord[i]]; oy[i] = py[ord[i]]; }
            float o[10];
            #pragma unroll
            for (int i = 0; i < 10; i++) o[i] = -1.f;
            o[0] = ox[0]; o[1] = oy[0];
            int dst = 1;
            for (int i = 1; i < 5; i++) {
                float d = fabsf(ox[i] - ox[i - 1]) + fabsf(oy[i] - oy[i - 1]);
                if (d != 0.f) { o[2 * dst] = ox[i]; o[2 * dst + 1] = oy[i]; dst++; }
            }
            float* op = out + (long long)gimg * 10;
            #pragma unroll
            for (int i = 0; i < 10; i++) op[i] = o[i];
        }
    }
}

extern "C" void kernel_launch(void* const* d_in, const int* in_sizes, int n_in,
                              void* d_out, int out_size) {
    const float* data = (const float*)d_in[0];
    const float* w1   = (const float*)d_in[1];
    const float* b1   = (const float*)d_in[2];
    const float* w2   = (const float*)d_in[3];
    const float* b2   = (const float*)d_in[4];
    const float* w3   = (const float*)d_in[5];
    const float* b3   = (const float*)d_in[6];
    const float* w4   = (const float*)d_in[7];
    const float* b4   = (const float*)d_in[8];
    const float* wd1  = (const float*)d_in[9];
    const float* bd1  = (const float*)d_in[10];
    const float* wd2  = (const float*)d_in[11];
    const float* bd2  = (const float*)d_in[12];
    float* out = (float*)d_out;
    const int B = in_sizes[0] / 100;

    cudaFuncSetAttribute(img2svg_mma, cudaFuncAttributeMaxDynamicSharedMemorySize, SMEM_TOTAL);

    convert_weights<<<96, 256>>>(w2, w3, w4);
    img2svg_mma<<<(B + 1) / 2, NT, SMEM_TOTAL>>>(data, w1, b1, b2, b3, b4,
                                                 wd1, bd1, wd2, bd2, out, B);
}

// round 17
// speedup vs baseline: 1.0907x; 1.0610x over previous
#include <cuda_runtime.h>
#include <cuda_bf16.h>
#include <cstdint>

#define NT 256

// Fragment-major bf16 weights: each uint4 = one lane's mma-A fragment (a0,a1,a2,a3)
__device__ uint4 g_w2f[18432];
__device__ uint4 g_w3f[9216];
__device__ uint4 g_w4f[4608];

__global__ void convert_weights(const float* __restrict__ w2,
                                const float* __restrict__ w3,
                                const float* __restrict__ w4) {
    int gid = blockIdx.x * blockDim.x + threadIdx.x;
    int stride = gridDim.x * blockDim.x;
    for (int u = gid; u < 18432; u += stride) {
        int lane = u & 31, k = (u >> 5) & 7, mb = (u >> 8) & 7, tap = u >> 11;
        int r = lane >> 2, c0 = (lane & 3) * 2;
        int co = mb * 16 + r, ci = k * 16 + c0;
        const float* Wt = w2 + tap * 16384;
        uint4 v;
        __nv_bfloat162 p;
        p = __floats2bfloat162_rn(Wt[ci * 128 + co],       Wt[(ci + 1) * 128 + co]);       v.x = *(uint32_t*)&p;
        p = __floats2bfloat162_rn(Wt[ci * 128 + co + 8],   Wt[(ci + 1) * 128 + co + 8]);   v.y = *(uint32_t*)&p;
        p = __floats2bfloat162_rn(Wt[(ci + 8) * 128 + co], Wt[(ci + 9) * 128 + co]);       v.z = *(uint32_t*)&p;
        p = __floats2bfloat162_rn(Wt[(ci + 8) * 128 + co + 8], Wt[(ci + 9) * 128 + co + 8]); v.w = *(uint32_t*)&p;
        g_w2f[u] = v;
    }
    for (int u = gid; u < 9216; u += stride) {
        int lane = u & 31, k = (u >> 5) & 7, mb = (u >> 8) & 3, tap = u >> 10;
        int r = lane >> 2, c0 = (lane & 3) * 2;
        int co = mb * 16 + r, ci = k * 16 + c0;
        const float* Wt = w3 + tap * 8192;
        uint4 v;
        __nv_bfloat162 p;
        p = __floats2bfloat162_rn(Wt[ci * 64 + co],       Wt[(ci + 1) * 64 + co]);       v.x = *(uint32_t*)&p;
        p = __floats2bfloat162_rn(Wt[ci * 64 + co + 8],   Wt[(ci + 1) * 64 + co + 8]);   v.y = *(uint32_t*)&p;
        p = __floats2bfloat162_rn(Wt[(ci + 8) * 64 + co], Wt[(ci + 9) * 64 + co]);       v.z = *(uint32_t*)&p;
        p = __floats2bfloat162_rn(Wt[(ci + 8) * 64 + co + 8], Wt[(ci + 9) * 64 + co + 8]); v.w = *(uint32_t*)&p;
        g_w3f[u] = v;
    }
    for (int u = gid; u < 4608; u += stride) {
        int lane = u & 31, k = (u >> 5) & 3, mb = (u >> 7) & 3, tap = u >> 9;
        int r = lane >> 2, c0 = (lane & 3) * 2;
        int co = mb * 16 + r, ci = k * 16 + c0;
        const float* Wt = w4 + tap * 4096;
        uint4 v;
        __nv_bfloat162 p;
        p = __floats2bfloat162_rn(Wt[ci * 64 + co],       Wt[(ci + 1) * 64 + co]);       v.x = *(uint32_t*)&p;
        p = __floats2bfloat162_rn(Wt[ci * 64 + co + 8],   Wt[(ci + 1) * 64 + co + 8]);   v.y = *(uint32_t*)&p;
        p = __floats2bfloat162_rn(Wt[(ci + 8) * 64 + co], Wt[(ci + 9) * 64 + co]);       v.z = *(uint32_t*)&p;
        p = __floats2bfloat162_rn(Wt[(ci + 8) * 64 + co + 8], Wt[(ci + 9) * 64 + co + 8]); v.w = *(uint32_t*)&p;
        g_w4f[u] = v;
    }
}

// ---------------- SMEM layout (byte offsets), 2 images per CTA ----------------
#define S_ACT1   0          // 2 x [100 pos][136 ci] bf16 (stride 272B) = 54400
#define S_POOL2  54400      // [50][136] bf16 stride 272 = 13600
#define S_ACT3   68000      // [50][72] bf16 stride 144 = 7200
#define S_ZERO   75200      // 272 zero row
#define S_B2     75472
#define S_B3     75984
#define S_B4     76240
#define S_BD1    76496
#define S_BD2    76624
#define S_WD2    76640
#define S_FEAT   77152
#define S_H      77664
#define S_SV     77920
#define S_IMG    77952      // 2 x 144 padded f32 images = 1152
#define SMEM_TOTAL 79104
#define S_ACT4   0          // act4 scratch [64co][104n] stride 208 (act1 dead)

__device__ __forceinline__ uint32_t smem_u32(const void* p) {
    uint32_t a;
    asm("{ .reg .u64 t; cvta.to.shared.u64 t, %1; cvt.u32.u64 %0, t; }" : "=r"(a) : "l"(p));
    return a;
}

__device__ __forceinline__ void mma16816(float* c, uint32_t a0, uint32_t a1, uint32_t a2,
                                         uint32_t a3, uint32_t b0, uint32_t b1) {
    asm volatile(
        "mma.sync.aligned.m16n8k16.row.col.f32.bf16.bf16.f32 "
        "{%0,%1,%2,%3},{%4,%5,%6,%7},{%8,%9},{%0,%1,%2,%3};\n"
        : "+f"(c[0]), "+f"(c[1]), "+f"(c[2]), "+f"(c[3])
        : "r"(a0), "r"(a1), "r"(a2), "r"(a3), "r"(b0), "r"(b1));
}

__device__ __forceinline__ void ldmx4(uint32_t& b0, uint32_t& b1, uint32_t& b2, uint32_t& b3,
                                      uint32_t addr) {
    asm volatile("ldmatrix.sync.aligned.m8n8.x4.shared.b16 {%0,%1,%2,%3},[%4];"
                 : "=r"(b0), "=r"(b1), "=r"(b2), "=r"(b3) : "r"(addr));
}

__global__ __launch_bounds__(NT, 2)
void img2svg_mma(const float* __restrict__ data,
                 const float* __restrict__ w1, const float* __restrict__ b1,
                 const float* __restrict__ b2v, const float* __restrict__ b3v,
                 const float* __restrict__ b4v,
                 const float* __restrict__ wd1, const float* __restrict__ bd1,
                 const float* __restrict__ wd2, const float* __restrict__ bd2,
                 float* __restrict__ out, int Btot) {
    extern __shared__ char sm[];
    const int tid = threadIdx.x;
    const int wid = tid >> 5, lane = tid & 31;
    const int dlt = lane >> 2, q = lane & 3;
    const uint32_t sbase = smem_u32(sm);
    const int rB = lane & 7;                             // B row (n) within frag
    const int hB = ((lane >> 3) & 1) * 16;               // k-half byte offset
    const int hiSel = lane >> 4;                          // 0: frag 2u, 1: frag 2u+1
    const uint32_t zAddr = sbase + (uint32_t)(S_ZERO + hB);

    float* s_b2  = (float*)(sm + S_B2);
    float* s_b3  = (float*)(sm + S_B3);
    float* s_b4  = (float*)(sm + S_B4);
    float* s_bd1 = (float*)(sm + S_BD1);
    float* s_bd2 = (float*)(sm + S_BD2);
    float* s_wd2 = (float*)(sm + S_WD2);
    float* s_feat = (float*)(sm + S_FEAT);
    float* s_h   = (float*)(sm + S_H);
    float* s_sv  = (float*)(sm + S_SV);
    float* s_img = (float*)(sm + S_IMG);   // 2 x [12x12] padded

    // ---- init loads ----
    if (tid < 128) s_b2[tid] = b2v[tid];
    if (tid < 64)  s_b3[tid] = b3v[tid];
    if (tid < 64)  s_b4[tid] = b4v[tid];
    if (tid < 32)  s_bd1[tid] = bd1[tid];
    if (tid < 4)   s_bd2[tid] = bd2[tid];
    if (tid < 128) s_wd2[tid] = wd2[tid];
    if (tid < 68)  *(uint32_t*)(sm + S_ZERO + tid * 4) = 0u;
    {
        // padded image fill: each element decides border vs interior (no race, one pass)
        for (int e = tid; e < 288; e += NT) {
            int img = e >= 144, pp = e - img * 144;
            int r = pp / 12, c = pp - r * 12;
            float v = 0.f;
            if (r >= 1 && r <= 10 && c >= 1 && c <= 10) {
                long long gi = (long long)blockIdx.x * 200 + img * 100 + (r - 1) * 10 + (c - 1);
                v = (gi < (long long)Btot * 100) ? data[gi] : 0.f;
            }
            s_img[e] = v;
        }
    }
    __syncthreads();

    // ---- conv1: padded, branch-free, div-free. 1 -> 128, relu -> act1 bf16 ----
    {
        const int img = tid >> 7, co = tid & 127;
        const float* ip = s_img + img * 144;
        float wv[9];
        #pragma unroll
        for (int t = 0; t < 9; t++) wv[t] = w1[t * 128 + co];
        const float bias = b1[co];
        char* dst0 = sm + S_ACT1 + img * 27200 + co * 2;
        for (int r = 0; r < 10; r++) {
            const float* p0 = ip + r * 12;
            char* drow = dst0 + (r * 10) * 272;
            #pragma unroll
            for (int c = 0; c < 10; c++) {
                float acc = bias;
                acc += wv[0] * p0[c];
                acc += wv[1] * p0[c + 1];
                acc += wv[2] * p0[c + 2];
                acc += wv[3] * p0[c + 12];
                acc += wv[4] * p0[c + 13];
                acc += wv[5] * p0[c + 14];
                acc += wv[6] * p0[c + 24];
                acc += wv[7] * p0[c + 25];
                acc += wv[8] * p0[c + 26];
                *(__nv_bfloat16*)(drow + c * 272) = __float2bfloat16(fmaxf(acc, 0.f));
            }
        }
    }
    __syncthreads();

    // ---- conv2: per pass 1 image x 8 warps, warp m32 x n56, K=128/tap, barrier-free ----
    for (int p = 0; p < 2; p++) {
        const int mg = wid >> 1, ng = wid & 1;
        const int njeff = ng ? 6 : 7;
        const int npair = ng ? 3 : 4;
        float C0[7][4], C1[7][4];
        #pragma unroll
        for (int j = 0; j < 7; j++)
            #pragma unroll
            for (int k = 0; k < 4; k++) { C0[j][k] = 0.f; C1[j][k] = 0.f; }

        int rj[7], cj[7];
        #pragma unroll
        for (int j = 0; j < 7; j++) {
            int n = ng * 56 + j * 8 + rB;
            rj[j] = (n < 100) ? (n / 10) : -100;
            cj[j] = n - (n / 10) * 10;
        }
        const uint32_t bBase = sbase + (uint32_t)(S_ACT1 + p * 27200 + hB);
        const uint4* W = g_w2f + (mg * 2) * 256 + lane;    // + t*2048 + mt*256 + k*32

        // continuous A prefetch across tap boundaries
        uint4 a0c = __ldg(W), a1c = __ldg(W + 256);
        for (int t = 0; t < 9; t++) {
            const int dy = t / 3 - 1, dx = t % 3 - 1;
            uint32_t bA[7];
            #pragma unroll
            for (int j = 0; j < 7; j++) {
                int rr = rj[j] + dy, cc = cj[j] + dx;
                bool ok = ((unsigned)rr < 10u) && ((unsigned)cc < 10u);
                bA[j] = ok ? bBase + (uint32_t)((rr * 10 + cc) * 272) : zAddr;
            }
            uint32_t bSel[4];
            bSel[0] = hiSel ? bA[1] : bA[0];
            bSel[1] = hiSel ? bA[3] : bA[2];
            bSel[2] = hiSel ? bA[5] : bA[4];
            bSel[3] = hiSel ? zAddr : bA[6];
            const uint4* Wt = W + t * 2048;
            #pragma unroll
            for (int k = 0; k < 8; k++) {
                const uint4* Wn = (k < 7) ? (Wt + (k + 1) * 32)
                                          : ((t < 8) ? (W + (t + 1) * 2048) : Wt);
                uint4 a0n = __ldg(Wn), a1n = __ldg(Wn + 256);
                #pragma unroll
                for (int u = 0; u < 4; u++) {
                    if (u < npair) {
                        uint32_t b0, b1, b2, b3;
                        ldmx4(b0, b1, b2, b3, bSel[u] + 32 * k);
                        mma16816(C0[2 * u], a0c.x, a0c.y, a0c.z, a0c.w, b0, b1);
                        mma16816(C1[2 * u], a1c.x, a1c.y, a1c.z, a1c.w, b0, b1);
                        if (2 * u + 1 < njeff) {
                            mma16816(C0[2 * u + 1], a0c.x, a0c.y, a0c.z, a0c.w, b2, b3);
                            mma16816(C1[2 * u + 1], a1c.x, a1c.y, a1c.z, a1c.w, b2, b3);
                        }
                    }
                }
                a0c = a0n; a1c = a1n;
            }
        }
        __syncthreads();   // all warps done reading act1[p]

        // epilogue: bias+relu -> scratch [co][104 n] (overlays act1 slot p)
        const uint32_t scr = S_ACT1 + (uint32_t)p * 27200;
        #pragma unroll
        for (int mt = 0; mt < 2; mt++) {
            #pragma unroll
            for (int j = 0; j < 7; j++) {
                float* c = mt ? C1[j] : C0[j];
                int co = mg * 32 + mt * 16 + dlt;
                int n0 = ng * 56 + j * 8 + 2 * q;
                if (n0 < 100) {
                    float bAv = s_b2[co], bBv = s_b2[co + 8];
                    __nv_bfloat162 v01 = __floats2bfloat162_rn(fmaxf(c[0] + bAv, 0.f),
                                                               fmaxf(c[1] + bAv, 0.f));
                    __nv_bfloat162 v23 = __floats2bfloat162_rn(fmaxf(c[2] + bBv, 0.f),
                                                               fmaxf(c[3] + bBv, 0.f));
                    *(uint32_t*)(sm + scr + co * 208 + n0 * 2) = *(uint32_t*)&v01;
                    *(uint32_t*)(sm + scr + (co + 8) * 208 + n0 * 2) = *(uint32_t*)&v23;
                }
            }
        }
        __syncthreads();
        // 2x2 maxpool -> pooled2[p*25+pp][ci]
        for (int e = tid; e < 3200; e += NT) {
            int co = e & 127, pp = e >> 7;
            int pr = pp / 5, pc = pp - pr * 5;
            int ntop = pr * 20 + pc * 2;
            uint32_t topw = *(uint32_t*)(sm + scr + co * 208 + ntop * 2);
            uint32_t botw = *(uint32_t*)(sm + scr + co * 208 + (ntop + 10) * 2);
            float2 tf = __bfloat1622float2(*(__nv_bfloat162*)&topw);
            float2 bf = __bfloat1622float2(*(__nv_bfloat162*)&botw);
            float m = fmaxf(fmaxf(tf.x, tf.y), fmaxf(bf.x, bf.y));
            *(__nv_bfloat16*)(sm + S_POOL2 + (p * 25 + pp) * 272 + co * 2) =
                __float2bfloat16(m);
        }
        __syncthreads();
    }

    // ---- conv3: M=64, N=50 (2img x 25pos), K=128/tap; 8 warps m32n16, barrier-free ----
    {
        const int mg = wid & 1, ng = wid >> 1;           // ng 0..3
        const int njeff = (ng == 3) ? 1 : 2;
        float D0[2][4], D1[2][4];
        #pragma unroll
        for (int j = 0; j < 2; j++)
            #pragma unroll
            for (int k = 0; k < 4; k++) { D0[j][k] = 0.f; D1[j][k] = 0.f; }

        int rj[2], cj[2];
        uint32_t aj[2];
        #pragma unroll
        for (int j = 0; j < 2; j++) {
            int n = ng * 16 + j * 8 + rB;
            int img = n / 25, pos = n - img * 25;
            rj[j] = (n < 50) ? (pos / 5) : -100;
            cj[j] = pos - (pos / 5) * 5;
            aj[j] = sbase + (uint32_t)(S_POOL2 + img * 25 * 272 + hB);
        }
        const uint4* W = g_w3f + (mg * 2) * 256 + lane;   // + t*1024 + mt*256 + k*32

        uint4 a0c = __ldg(W), a1c = __ldg(W + 256);
        for (int t = 0; t < 9; t++) {
            const int dy = t / 3 - 1, dx = t % 3 - 1;
            uint32_t bA[2];
            #pragma unroll
            for (int j = 0; j < 2; j++) {
                int rr = rj[j] + dy, cc = cj[j] + dx;
                bool ok = ((unsigned)rr < 5u) && ((unsigned)cc < 5u);
                bA[j] = ok ? aj[j] + (uint32_t)((rr * 5 + cc) * 272) : zAddr;
            }
            uint32_t bSel = hiSel ? ((njeff > 1) ? bA[1] : zAddr) : bA[0];
            const uint4* Wt = W + t * 1024;
            #pragma unroll
            for (int k = 0; k < 8; k++) {
                const uint4* Wn = (k < 7) ? (Wt + (k + 1) * 32)
                                          : ((t < 8) ? (W + (t + 1) * 1024) : Wt);
                uint4 a0n = __ldg(Wn), a1n = __ldg(Wn + 256);
                uint32_t b0, b1, b2, b3;
                ldmx4(b0, b1, b2, b3, bSel + 32 * k);
                mma16816(D0[0], a0c.x, a0c.y, a0c.z, a0c.w, b0, b1);
                mma16816(D1[0], a1c.x, a1c.y, a1c.z, a1c.w, b0, b1);
                if (njeff > 1) {
                    mma16816(D0[1], a0c.x, a0c.y, a0c.z, a0c.w, b2, b3);
                    mma16816(D1[1], a1c.x, a1c.y, a1c.z, a1c.w, b2, b3);
                }
                a0c = a0n; a1c = a1n;
            }
        }
        __syncthreads();
        #pragma unroll
        for (int mt = 0; mt < 2; mt++) {
            #pragma unroll
            for (int j = 0; j < 2; j++) {
                float* c = mt ? D1[j] : D0[j];
                int co = mg * 32 + mt * 16 + dlt;
                int n0 = ng * 16 + j * 8 + 2 * q;
                if (n0 < 50) {
                    float bAv = s_b3[co], bBv = s_b3[co + 8];
                    *(__nv_bfloat16*)(sm + S_ACT3 + n0 * 144 + co * 2) =
                        __float2bfloat16(fmaxf(c[0] + bAv, 0.f));
                    *(__nv_bfloat16*)(sm + S_ACT3 + (n0 + 1) * 144 + co * 2) =
                        __float2bfloat16(fmaxf(c[1] + bAv, 0.f));
                    *(__nv_bfloat16*)(sm + S_ACT3 + n0 * 144 + (co + 8) * 2) =
                        __float2bfloat16(fmaxf(c[2] + bBv, 0.f));
                    *(__nv_bfloat16*)(sm + S_ACT3 + (n0 + 1) * 144 + (co + 8) * 2) =
                        __float2bfloat16(fmaxf(c[3] + bBv, 0.f));
                }
            }
        }
        __syncthreads();
    }

    // ---- conv4: M=64, N=50, K=64/tap; 8 warps m32n16, barrier-free ----
    {
        const int mg = wid & 1, ng = wid >> 1;
        const int njeff = (ng == 3) ? 1 : 2;
        float D0[2][4], D1[2][4];
        #pragma unroll
        for (int j = 0; j < 2; j++)
            #pragma unroll
            for (int k = 0; k < 4; k++) { D0[j][k] = 0.f; D1[j][k] = 0.f; }

        int rj[2], cj[2];
        uint32_t aj[2];
        #pragma unroll
        for (int j = 0; j < 2; j++) {
            int n = ng * 16 + j * 8 + rB;
            int img = n / 25, pos = n - img * 25;
            rj[j] = (n < 50) ? (pos / 5) : -100;
            cj[j] = pos - (pos / 5) * 5;
            aj[j] = sbase + (uint32_t)(S_ACT3 + img * 25 * 144 + hB);
        }
        const uint4* W = g_w4f + (mg * 2) * 128 + lane;   // + t*512 + mt*128 + k*32

        uint4 a0c = __ldg(W), a1c = __ldg(W + 128);
        for (int t = 0; t < 9; t++) {
            const int dy = t / 3 - 1, dx = t % 3 - 1;
            uint32_t bA[2];
            #pragma unroll
            for (int j = 0; j < 2; j++) {
                int rr = rj[j] + dy, cc = cj[j] + dx;
                bool ok = ((unsigned)rr < 5u) && ((unsigned)cc < 5u);
                bA[j] = ok ? aj[j] + (uint32_t)((rr * 5 + cc) * 144) : zAddr;
            }
            uint32_t bSel = hiSel ? ((njeff > 1) ? bA[1] : zAddr) : bA[0];
            const uint4* Wt = W + t * 512;
            #pragma unroll
            for (int k = 0; k < 4; k++) {
                const uint4* Wn = (k < 3) ? (Wt + (k + 1) * 32)
                                          : ((t < 8) ? (W + (t + 1) * 512) : Wt);
                uint4 a0n = __ldg(Wn), a1n = __ldg(Wn + 128);
                uint32_t b0, b1, b2, b3;
                ldmx4(b0, b1, b2, b3, bSel + 32 * k);
                mma16816(D0[0], a0c.x, a0c.y, a0c.z, a0c.w, b0, b1);
                mma16816(D1[0], a1c.x, a1c.y, a1c.z, a1c.w, b0, b1);
                if (njeff > 1) {
                    mma16816(D0[1], a0c.x, a0c.y, a0c.z, a0c.w, b2, b3);
                    mma16816(D1[1], a1c.x, a1c.y, a1c.z, a1c.w, b2, b3);
                }
                a0c = a0n; a1c = a1n;
            }
        }
        __syncthreads();
        #pragma unroll
        for (int mt = 0; mt < 2; mt++) {
            #pragma unroll
            for (int j = 0; j < 2; j++) {
                float* c = mt ? D1[j] : D0[j];
                int co = mg * 32 + mt * 16 + dlt;
                int n0 = ng * 16 + j * 8 + 2 * q;
                if (n0 < 50) {
                    float bAv = s_b4[co], bBv = s_b4[co + 8];
                    __nv_bfloat162 v01 = __floats2bfloat162_rn(fmaxf(c[0] + bAv, 0.f),
                                                               fmaxf(c[1] + bAv, 0.f));
                    __nv_bfloat162 v23 = __floats2bfloat162_rn(fmaxf(c[2] + bBv, 0.f),
                                                               fmaxf(c[3] + bBv, 0.f));
                    *(uint32_t*)(sm + S_ACT4 + co * 208 + n0 * 2) = *(uint32_t*)&v01;
                    *(uint32_t*)(sm + S_ACT4 + (co + 8) * 208 + n0 * 2) = *(uint32_t*)&v23;
                }
            }
        }
        __syncthreads();
    }

    // ---- head: pool 2x2 -> mean -> dense -> sigmoid ----
    if (tid < 128) {
        int img = tid >> 6, c = tid & 63;
        const char* b = sm + S_ACT4 + c * 208 + img * 50;
        #define GA(p) __bfloat162float(*(const __nv_bfloat16*)(b + (p) * 2))
        float m00 = fmaxf(fmaxf(GA(0), GA(1)), fmaxf(GA(5), GA(6)));
        float m01 = fmaxf(fmaxf(GA(2), GA(3)), fmaxf(GA(7), GA(8)));
        float m10 = fmaxf(fmaxf(GA(10), GA(11)), fmaxf(GA(15), GA(16)));
        float m11 = fmaxf(fmaxf(GA(12), GA(13)), fmaxf(GA(17), GA(18)));
        #undef GA
        s_feat[img * 64 + c] = 0.25f * (m00 + m01 + m10 + m11);
    }
    __syncthreads();
    if (tid < 64) {
        int img = tid >> 5, jn = tid & 31;
        float acc = s_bd1[jn];
        #pragma unroll 8
        for (int c = 0; c < 64; c++) acc += s_feat[img * 64 + c] * __ldg(wd1 + c * 32 + jn);
        s_h[img * 32 + jn] = fmaxf(acc, 0.f);
    }
    __syncthreads();
    if (tid < 8) {
        int img = tid >> 2, k = tid & 3;
        float acc = s_bd2[k];
        #pragma unroll 8
        for (int j = 0; j < 32; j++) acc += s_h[img * 32 + j] * s_wd2[j * 4 + k];
        s_sv[img * 4 + k] = 1.f / (1.f + expf(-acc));
    }
    __syncthreads();
    if (tid < 2) {
        int gimg = blockIdx.x * 2 + tid;
        if (gimg < Btot) {
            const float* sv = s_sv + tid * 4;
            const float p1x = sv[0], p1y = sv[1], p2x = sv[2], p2y = sv[3];
            float px[5], py[5], pos[5];
            #pragma unroll
            for (int i = 0; i < 5; i++) {
                float t = 0.25f * (float)i;
                float x = rintf(((1.f - t) * p1x + t * p2x) * 10.f);
                float y = rintf(((1.f - t) * p1y + t * p2y) * 10.f);
                px[i] = x; py[i] = y;
                pos[i] = x * 10.f + y;
            }
            int ord[5] = {0, 1, 2, 3, 4};
            for (int i = 1; i < 5; i++) {
                int key = ord[i]; float kp = pos[key]; int j = i - 1;
                while (j >= 0 && pos[ord[j]] > kp) { ord[j + 1] = ord[j]; j--; }
                ord[j + 1] = key;
            }
            float ox[5], oy[5];
            #pragma unroll
            for (int i = 0; i < 5; i++) { ox[i] = px[ord[i]]; oy[i] = py[ord[i]]; }
            float o[10];
            #pragma unroll
            for (int i = 0; i < 10; i++) o[i] = -1.f;
            o[0] = ox[0]; o[1] = oy[0];
            int dst = 1;
            for (int i = 1; i < 5; i++) {
                float d = fabsf(ox[i] - ox[i - 1]) + fabsf(oy[i] - oy[i - 1]);
                if (d != 0.f) { o[2 * dst] = ox[i]; o[2 * dst + 1] = oy[i]; dst++; }
            }
            float* op = out + (long long)gimg * 10;
            #pragma unroll
            for (int i = 0; i < 10; i++) op[i] = o[i];
        }
    }
}

extern "C" void kernel_launch(void* const* d_in, const int* in_sizes, int n_in,
                              void* d_out, int out_size) {
    const float* data = (const float*)d_in[0];
    const float* w1   = (const float*)d_in[1];
    const float* b1   = (const float*)d_in[2];
    const float* w2   = (const float*)d_in[3];
    const float* b2   = (const float*)d_in[4];
    const float* w3   = (const float*)d_in[5];
    const float* b3   = (const float*)d_in[6];
    const float* w4   = (const float*)d_in[7];
    const float* b4   = (const float*)d_in[8];
    const float* wd1  = (const float*)d_in[9];
    const float* bd1  = (const float*)d_in[10];
    const float* wd2  = (const float*)d_in[11];
    const float* bd2  = (const float*)d_in[12];
    float* out = (float*)d_out;
    const int B = in_sizes[0] / 100;

    cudaFuncSetAttribute(img2svg_mma, cudaFuncAttributeMaxDynamicSharedMemorySize, SMEM_TOTAL);

    convert_weights<<<96, 256>>>(w2, w3, w4);
    img2svg_mma<<<(B + 1) / 2, NT, SMEM_TOTAL>>>(data, w1, b1, b2, b3, b4,
                                                 wd1, bd1, wd2, bd2, out, B);
}